// round 14
// baseline (speedup 1.0000x reference)
#include <cuda_runtime.h>
#include <cuda_bf16.h>
#include <cstdint>
#include <math.h>

#define B_   8
#define N_   1024
#define C_   768
#define H_   12
#define HID_ 3072
#define RN_  513
#define MROWS (B_*RN_)   // 4104

// ---------------- scratch (static __device__, no allocation) ----------------
__device__ float g_XN  [B_*N_*C_];
__device__ float g_QKV [B_*N_*3*C_];   // K,V region (cols 768..2303) used
__device__ float g_QG  [MROWS*C_];
__device__ float g_XATT[MROWS*C_];
__device__ float g_CLSH[B_*H_*(N_-1)];
__device__ int   g_ROWSEL[B_*RN_];
__device__ float g_XP  [MROWS*C_];
__device__ float g_XN2 [MROWS*C_];
__device__ float g_HB  [MROWS*HID_];

__device__ __forceinline__ float gelu_exact(float v) {
    return 0.5f * v * (1.0f + erff(v * 0.70710678118654752f));
}

// ---------------- LayerNorm (1 row / block, C=768, 256 threads) -------------
__global__ __launch_bounds__(256) void ln_kernel(
    const float* __restrict__ X, const float* __restrict__ g,
    const float* __restrict__ bt, float* __restrict__ Y)
{
    __shared__ float red[8];
    int row = blockIdx.x, t = threadIdx.x;
    const float* xr = X + (size_t)row * C_;
    float x0 = xr[t], x1 = xr[t+256], x2 = xr[t+512];
    float s = x0 + x1 + x2;
    #pragma unroll
    for (int o = 16; o; o >>= 1) s += __shfl_xor_sync(~0u, s, o);
    if ((t & 31) == 0) red[t >> 5] = s;
    __syncthreads();
    float tot = 0.f;
    #pragma unroll
    for (int i = 0; i < 8; i++) tot += red[i];
    float mean = tot * (1.0f/768.0f);
    __syncthreads();
    float d0 = x0-mean, d1 = x1-mean, d2 = x2-mean;
    float q = d0*d0 + d1*d1 + d2*d2;
    #pragma unroll
    for (int o = 16; o; o >>= 1) q += __shfl_xor_sync(~0u, q, o);
    if ((t & 31) == 0) red[t >> 5] = q;
    __syncthreads();
    float tq = 0.f;
    #pragma unroll
    for (int i = 0; i < 8; i++) tq += red[i];
    float rstd = 1.0f / sqrtf(tq * (1.0f/768.0f) + 1e-5f);
    float* yr = Y + (size_t)row * C_;
    yr[t]     = d0*rstd*g[t]     + bt[t];
    yr[t+256] = d1*rstd*g[t+256] + bt[t+256];
    yr[t+512] = d2*rstd*g[t+512] + bt[t+512];
}

// ------- fp32 SGEMM w/ strides (exact path for K): 128x128x8, 8x8 ----------
template<bool GATHER>
__global__ __launch_bounds__(256) void sgemm2(
    const float* __restrict__ A, int lda,
    const float* __restrict__ Bm, int ldb,
    float* __restrict__ Cm, int ldc,
    int M, int N, int K, const int* __restrict__ rowmap)
{
    __shared__ float As[8][128];
    __shared__ float Bs[8][128];
    int t = threadIdx.x;
    int row0 = blockIdx.y * 128, col0 = blockIdx.x * 128;

    int la_r = t >> 1, la_k = (t & 1) * 4;
    long a_base = -1;
    {
        int arow = row0 + la_r;
        if (arow < M) a_base = (long)(GATHER ? rowmap[arow] : arow) * lda;
    }
    int lb_k = t >> 5, lb_c = (t & 31) * 4;
    const float* bp = Bm + (size_t)lb_k * ldb + col0 + lb_c;

    int ty = t >> 4, tx = t & 15;
    float acc[8][8] = {{0.f}};

    float4 av = make_float4(0.f,0.f,0.f,0.f), bv;
    if (a_base >= 0) av = *(const float4*)(A + a_base + la_k);
    bv = *(const float4*)bp;

    for (int k0 = 0; k0 < K; k0 += 8) {
        __syncthreads();
        As[la_k  ][la_r] = av.x;  As[la_k+1][la_r] = av.y;
        As[la_k+2][la_r] = av.z;  As[la_k+3][la_r] = av.w;
        *(float4*)&Bs[lb_k][lb_c] = bv;
        __syncthreads();
        if (k0 + 8 < K) {
            if (a_base >= 0) av = *(const float4*)(A + a_base + k0 + 8 + la_k);
            bv = *(const float4*)(bp + (size_t)(k0 + 8) * ldb);
        }
        #pragma unroll
        for (int kk = 0; kk < 8; kk++) {
            float4 a0 = *(const float4*)&As[kk][ty*8];
            float4 a1 = *(const float4*)&As[kk][ty*8+4];
            float4 b0 = *(const float4*)&Bs[kk][tx*8];
            float4 b1 = *(const float4*)&Bs[kk][tx*8+4];
            float ar[8] = {a0.x,a0.y,a0.z,a0.w,a1.x,a1.y,a1.z,a1.w};
            float br[8] = {b0.x,b0.y,b0.z,b0.w,b1.x,b1.y,b1.z,b1.w};
            #pragma unroll
            for (int i = 0; i < 8; i++)
                #pragma unroll
                for (int j = 0; j < 8; j++)
                    acc[i][j] = fmaf(ar[i], br[j], acc[i][j]);
        }
    }

    #pragma unroll
    for (int i = 0; i < 8; i++) {
        int row = row0 + ty*8 + i;
        if (row < M) {
            #pragma unroll
            for (int jj = 0; jj < 8; jj += 4) {
                int col = col0 + tx*8 + jj;
                float4 v = make_float4(acc[i][jj], acc[i][jj+1], acc[i][jj+2], acc[i][jj+3]);
                *(float4*)&Cm[(size_t)row * ldc + col] = v;
            }
        }
    }
}

// ============ bf16x3 MMA GEMM (m16n8k16 + ldmatrix), 128x128, BK=32 =========
// 8 warps 2(M)x4(N), warp tile 64x32. Error ~2^-17 (post-topk path only).
// EPI: 0 plain, 1 +bias+resid, 2 +bias+GELU. GA: gather A rows; GR: gather resid.
#define LDSM_X4(r0,r1,r2,r3,addr) \
    asm volatile("ldmatrix.sync.aligned.m8n8.x4.shared.b16 {%0,%1,%2,%3},[%4];" \
        : "=r"(r0),"=r"(r1),"=r"(r2),"=r"(r3) : "r"(addr))
#define LDSM_X4T(r0,r1,r2,r3,addr) \
    asm volatile("ldmatrix.sync.aligned.m8n8.x4.trans.shared.b16 {%0,%1,%2,%3},[%4];" \
        : "=r"(r0),"=r"(r1),"=r"(r2),"=r"(r3) : "r"(addr))

__device__ __forceinline__ void mma_bf16(float* c, const uint32_t* a,
                                         uint32_t b0, uint32_t b1) {
    asm volatile(
        "mma.sync.aligned.m16n8k16.row.col.f32.bf16.bf16.f32 "
        "{%0,%1,%2,%3},{%4,%5,%6,%7},{%8,%9},{%0,%1,%2,%3};"
        : "+f"(c[0]), "+f"(c[1]), "+f"(c[2]), "+f"(c[3])
        : "r"(a[0]), "r"(a[1]), "r"(a[2]), "r"(a[3]), "r"(b0), "r"(b1));
}

__device__ __forceinline__ void cvt16(const float* v, uint32_t* uh, uint32_t* ul) {
    #pragma unroll
    for (int p = 0; p < 8; p++) {
        float a = v[2*p], b = v[2*p+1];
        __nv_bfloat16 ha = __float2bfloat16(a), hb = __float2bfloat16(b);
        __nv_bfloat162 hi2; hi2.x = ha; hi2.y = hb;
        __nv_bfloat162 lo2 = __floats2bfloat162_rn(
            a - __bfloat162float(ha), b - __bfloat162float(hb));
        uh[p] = *(uint32_t*)&hi2;
        ul[p] = *(uint32_t*)&lo2;
    }
}

// smem: A rows 128, stride 80B (64B data + 16 pad); B rows 32 (k), stride 272B
#define A_STR 80
#define B_STR 272

template<bool GA, bool GR, int EPI>
__global__ __launch_bounds__(256) void bf_gemm(
    const float* __restrict__ A, int lda,
    const float* __restrict__ Bm, int ldb,
    float* __restrict__ Cm, int ldc,
    int M, int N, int K,
    const float* __restrict__ bias, const float* __restrict__ resid,
    const int* __restrict__ rowmap)
{
    __shared__ __align__(16) char sAh[128*A_STR];
    __shared__ __align__(16) char sAl[128*A_STR];
    __shared__ __align__(16) char sBh[32*B_STR];
    __shared__ __align__(16) char sBl[32*B_STR];

    const int t = threadIdx.x;
    const int lane = t & 31, wid = t >> 5;
    const int lq = lane >> 2, lr = lane & 3;
    const int wm = wid & 1,  wn = wid >> 1;
    const int row0 = blockIdx.y * 128, col0 = blockIdx.x * 128;

    // ---- loader mapping
    const int la_r = t >> 1, la_half = (t & 1);       // A: row, k-half(16)
    const int lb_k = t >> 3, lb_n = (t & 7) * 16;     // B: k-row, n-offset
    long a_base = -1;
    {
        int arow = row0 + la_r;
        if (arow < M) a_base = (long)(GA ? rowmap[arow] : arow) * lda;
    }
    const float* bptr = Bm + (size_t)lb_k * ldb + col0 + lb_n;

    // ---- ldmatrix per-thread addresses
    uint32_t a_h_base, a_l_base, b_h_base, b_l_base;
    {
        uint32_t sa;
        asm("{ .reg .u64 tt; cvta.to.shared.u64 tt, %1; cvt.u32.u64 %0, tt; }"
            : "=r"(sa) : "l"((void*)sAh));
        uint32_t arow = wm*64 + ((lane>>3)&1)*8 + (lane&7);
        uint32_t aoff = arow*A_STR + (lane>>4)*16;
        a_h_base = sa + aoff;
        asm("{ .reg .u64 tt; cvta.to.shared.u64 tt, %1; cvt.u32.u64 %0, tt; }"
            : "=r"(sa) : "l"((void*)sAl));
        a_l_base = sa + aoff;
        uint32_t brow = ((lane>>3)&1)*8 + (lane&7);
        uint32_t boff = brow*B_STR + wn*64 + (lane>>4)*16;
        asm("{ .reg .u64 tt; cvta.to.shared.u64 tt, %1; cvt.u32.u64 %0, tt; }"
            : "=r"(sa) : "l"((void*)sBh));
        b_h_base = sa + boff;
        asm("{ .reg .u64 tt; cvta.to.shared.u64 tt, %1; cvt.u32.u64 %0, tt; }"
            : "=r"(sa) : "l"((void*)sBl));
        b_l_base = sa + boff;
    }

    float acc[4][4][4];
    #pragma unroll
    for (int i = 0; i < 4; i++)
        #pragma unroll
        for (int j = 0; j < 4; j++)
            #pragma unroll
            for (int q = 0; q < 4; q++) acc[i][j][q] = 0.f;

    float av[16], bv[16];
    auto ldg = [&](int kt) {
        int k0 = kt * 32 + la_half * 16;
        if (a_base >= 0) {
            #pragma unroll
            for (int j = 0; j < 4; j++)
                *(float4*)&av[j*4] = *(const float4*)(A + a_base + k0 + j*4);
        } else {
            #pragma unroll
            for (int j = 0; j < 16; j++) av[j] = 0.f;
        }
        const float* bp = bptr + (size_t)(kt*32) * ldb;
        #pragma unroll
        for (int j = 0; j < 4; j++)
            *(float4*)&bv[j*4] = *(const float4*)(bp + j*4);
    };

    const int KT = K >> 5;
    ldg(0);

    for (int kt = 0; kt < KT; ++kt) {
        // store current tile (hi/lo split) to smem
        {
            uint32_t uh[8], ul[8];
            cvt16(av, uh, ul);
            char* pa = sAh + la_r*A_STR + la_half*32;
            *(uint4*)pa        = make_uint4(uh[0],uh[1],uh[2],uh[3]);
            *(uint4*)(pa + 16) = make_uint4(uh[4],uh[5],uh[6],uh[7]);
            pa = sAl + la_r*A_STR + la_half*32;
            *(uint4*)pa        = make_uint4(ul[0],ul[1],ul[2],ul[3]);
            *(uint4*)(pa + 16) = make_uint4(ul[4],ul[5],ul[6],ul[7]);
            cvt16(bv, uh, ul);
            char* pb = sBh + lb_k*B_STR + lb_n*2;
            *(uint4*)pb        = make_uint4(uh[0],uh[1],uh[2],uh[3]);
            *(uint4*)(pb + 16) = make_uint4(uh[4],uh[5],uh[6],uh[7]);
            pb = sBl + lb_k*B_STR + lb_n*2;
            *(uint4*)pb        = make_uint4(ul[0],ul[1],ul[2],ul[3]);
            *(uint4*)(pb + 16) = make_uint4(ul[4],ul[5],ul[6],ul[7]);
        }
        __syncthreads();
        if (kt + 1 < KT) ldg(kt + 1);

        #pragma unroll
        for (int ks = 0; ks < 2; ks++) {
            uint32_t ah[4][4], al_[4][4], bh[4][2], bl_[4][2];
            #pragma unroll
            for (int mf = 0; mf < 4; mf++) {
                uint32_t aa = a_h_base + mf*(16*A_STR) + ks*32;
                LDSM_X4(ah[mf][0],ah[mf][1],ah[mf][2],ah[mf][3], aa);
                aa = a_l_base + mf*(16*A_STR) + ks*32;
                LDSM_X4(al_[mf][0],al_[mf][1],al_[mf][2],al_[mf][3], aa);
            }
            #pragma unroll
            for (int nfp = 0; nfp < 2; nfp++) {
                uint32_t bb = b_h_base + ks*(16*B_STR) + nfp*32;
                LDSM_X4T(bh[2*nfp][0], bh[2*nfp][1], bh[2*nfp+1][0], bh[2*nfp+1][1], bb);
                bb = b_l_base + ks*(16*B_STR) + nfp*32;
                LDSM_X4T(bl_[2*nfp][0], bl_[2*nfp][1], bl_[2*nfp+1][0], bl_[2*nfp+1][1], bb);
            }
            #pragma unroll
            for (int mf = 0; mf < 4; mf++)
                #pragma unroll
                for (int nf = 0; nf < 4; nf++) {
                    float* c = acc[mf][nf];
                    mma_bf16(c, ah[mf],  bh[nf][0],  bh[nf][1]);
                    mma_bf16(c, ah[mf],  bl_[nf][0], bl_[nf][1]);
                    mma_bf16(c, al_[mf], bh[nf][0],  bh[nf][1]);
                }
        }
        __syncthreads();
    }

    // ---- epilogue (same fragment layout as m16n8 tf32 version)
    #pragma unroll
    for (int mf = 0; mf < 4; mf++) {
        int rbase = row0 + wm*64 + mf*16 + lq;
        #pragma unroll
        for (int half = 0; half < 2; half++) {
            int row = rbase + half*8;
            if (row < M) {
                long rres = 0;
                if (EPI == 1) rres = (long)(GR ? rowmap[row] : row) * N;
                #pragma unroll
                for (int nf = 0; nf < 4; nf++) {
                    int col = col0 + wn*32 + nf*8 + lr*2;
                    float v0 = acc[mf][nf][half*2+0];
                    float v1 = acc[mf][nf][half*2+1];
                    if (EPI != 0) { v0 += bias[col]; v1 += bias[col+1]; }
                    if (EPI == 2) { v0 = gelu_exact(v0); v1 = gelu_exact(v1); }
                    if (EPI == 1) { v0 += resid[rres+col]; v1 += resid[rres+col+1]; }
                    *(float2*)&Cm[(size_t)row * ldc + col] = make_float2(v0, v1);
                }
            }
        }
    }
}

// ------------- cls attention row (q0 = xn0 @ Wq, softmax, -> CLSH) ----------
__global__ __launch_bounds__(256) void cls_kernel(
    const float* __restrict__ XN, const float* __restrict__ wqkv,
    const float* __restrict__ QKV, const float* __restrict__ amask,
    float* __restrict__ CLSH)
{
    __shared__ float q0[64];
    __shared__ float sS[1024];
    __shared__ float red[8];
    int h = blockIdx.x, b = blockIdx.y, t = threadIdx.x;

    {
        int d = t >> 2, part = t & 3;
        const float* xr = XN + (size_t)b * N_ * C_;
        const float* wc = wqkv + h*64 + d;
        float s = 0.f;
        int k0 = part * 192;
        for (int k = k0; k < k0 + 192; k++)
            s = fmaf(xr[k], wc[(size_t)k * 2304], s);
        s += __shfl_xor_sync(~0u, s, 1);
        s += __shfl_xor_sync(~0u, s, 2);
        if (part == 0) q0[d] = s;
    }
    __syncthreads();

    float sv[4];
    #pragma unroll
    for (int j = 0; j < 4; j++) {
        int m = t + 256*j;
        const float* kr = QKV + (size_t)(b*N_ + m)*2304 + 768 + h*64;
        float acc = 0.f;
        #pragma unroll
        for (int d = 0; d < 64; d++) acc = fmaf(q0[d], kr[d], acc);
        sv[j] = acc * 0.125f;
    }
    float mx = fmaxf(fmaxf(sv[0], sv[1]), fmaxf(sv[2], sv[3]));
    #pragma unroll
    for (int o = 16; o; o >>= 1) mx = fmaxf(mx, __shfl_xor_sync(~0u, mx, o));
    if ((t & 31) == 0) red[t >> 5] = mx;
    __syncthreads();
    mx = red[0];
    #pragma unroll
    for (int i = 1; i < 8; i++) mx = fmaxf(mx, red[i]);

    const float* mrow = amask + (size_t)b * N_ * N_;
    float sum = 0.f;
    #pragma unroll
    for (int j = 0; j < 4; j++) {
        int m = t + 256*j;
        float e = expf(sv[j] - mx) * mrow[m];
        sS[m] = e;
        sum += e;
    }
    #pragma unroll
    for (int o = 16; o; o >>= 1) sum += __shfl_xor_sync(~0u, sum, o);
    __syncthreads();
    if ((t & 31) == 0) red[t >> 5] = sum;
    __syncthreads();
    sum = 0.f;
    #pragma unroll
    for (int i = 0; i < 8; i++) sum += red[i];
    float rinv = 1.0f / (sum + 1e-6f);
    const float epsn = 1e-6f / 1024.0f;
    float* cl = CLSH + (size_t)(b*H_ + h) * (N_ - 1);
    #pragma unroll
    for (int j = 0; j < 4; j++) {
        int m = t + 256*j;
        if (m >= 1) cl[m-1] = (sS[m] + epsn) * rinv;
    }
}

// --------- Attention for SELECTED rows: block = (32 compact rows, h, b) -----
__global__ __launch_bounds__(256) void attn_sel_kernel(
    const float* __restrict__ QG, const float* __restrict__ QKV,
    const float* __restrict__ amask, const int* __restrict__ ROWSEL,
    float* __restrict__ XATT)
{
    extern __shared__ float smx[];
    float* sS  = smx;                 // 32*1024
    float* sQt = smx + 32*1024;       // [64][36]
    float* sT  = sQt + 64*36;         // 8448 floats
    int t = threadIdx.x;
    int n0 = blockIdx.x * 32, h = blockIdx.y, b = blockIdx.z;
    size_t base_bh = (size_t)b * N_ * 2304 + (size_t)h * 64;

    for (int e = t; e < 32*64; e += 256) {
        int i = e >> 6, d = e & 63;
        int r = n0 + i;
        sQt[d*36 + i] = (r < RN_)
            ? QG[(size_t)(b*RN_ + r) * C_ + h*64 + d] : 0.f;
    }

    int ty = t >> 5, tx = t & 31;

    for (int kt = 0; kt < 8; kt++) {
        int m0 = kt << 7;
        __syncthreads();
        for (int e = t; e < 128*64; e += 256) {
            int m = e >> 6, d = e & 63;
            sT[d*132 + m] = QKV[base_bh + 768 + (size_t)(m0 + m) * 2304 + d];
        }
        __syncthreads();
        float acc[4][4] = {{0.f}};
        #pragma unroll 4
        for (int d = 0; d < 64; d++) {
            float4 aq = *(const float4*)&sQt[d*36 + ty*4];
            float4 bk = *(const float4*)&sT[d*132 + tx*4];
            float ar[4] = {aq.x,aq.y,aq.z,aq.w};
            float br[4] = {bk.x,bk.y,bk.z,bk.w};
            #pragma unroll
            for (int i = 0; i < 4; i++)
                #pragma unroll
                for (int j = 0; j < 4; j++)
                    acc[i][j] = fmaf(ar[i], br[j], acc[i][j]);
        }
        #pragma unroll
        for (int i = 0; i < 4; i++) {
            float4 v = make_float4(acc[i][0]*0.125f, acc[i][1]*0.125f,
                                   acc[i][2]*0.125f, acc[i][3]*0.125f);
            *(float4*)&sS[(ty*4+i)*1024 + m0 + tx*4] = v;
        }
    }
    __syncthreads();

    int lane = t & 31, w = t >> 5;
    for (int rr = 0; rr < 4; rr++) {
        int i = w + rr*8;
        int r = n0 + i;
        if (r >= RN_) continue;
        int norig = ROWSEL[b*RN_ + r] - b*1024;
        float* row = sS + i*1024;
        float mx = -3.4e38f;
        for (int m = lane; m < 1024; m += 32) mx = fmaxf(mx, row[m]);
        #pragma unroll
        for (int o = 16; o; o >>= 1) mx = fmaxf(mx, __shfl_xor_sync(~0u, mx, o));
        const float* mrow = amask + (size_t)(b * N_ + norig) * N_;
        float sum = 0.f;
        for (int m = lane; m < 1024; m += 32) {
            float e = expf(row[m] - mx) * mrow[m];
            row[m] = e;
            sum += e;
        }
        #pragma unroll
        for (int o = 16; o; o >>= 1) sum += __shfl_xor_sync(~0u, sum, o);
        float rinv = 1.0f / (sum + 1e-6f);
        const float epsn = 1e-6f / 1024.0f;
        for (int m = lane; m < 1024; m += 32) row[m] = (row[m] + epsn) * rinv;
    }
    __syncthreads();

    float oacc[4][2] = {{0.f}};
    for (int vt = 0; vt < 8; vt++) {
        int m0 = vt << 7;
        __syncthreads();
        for (int e = t; e < 128*64; e += 256) {
            int m = e >> 6, d = e & 63;
            sT[m*66 + d] = QKV[base_bh + 1536 + (size_t)(m0 + m) * 2304 + d];
        }
        __syncthreads();
        #pragma unroll 4
        for (int m = 0; m < 128; m++) {
            float2 vv = *(const float2*)&sT[m*66 + tx*2];
            #pragma unroll
            for (int i = 0; i < 4; i++) {
                float a = sS[(ty*4+i)*1024 + m0 + m];
                oacc[i][0] = fmaf(a, vv.x, oacc[i][0]);
                oacc[i][1] = fmaf(a, vv.y, oacc[i][1]);
            }
        }
    }
    #pragma unroll
    for (int i = 0; i < 4; i++) {
        int r = n0 + ty*4 + i;
        if (r < RN_) {
            float2 o2 = make_float2(oacc[i][0], oacc[i][1]);
            *(float2*)&XATT[(size_t)(b*RN_ + r) * C_ + h*64 + tx*2] = o2;
        }
    }
}

// ---------------- top-k via bitonic sort (jax.lax.top_k semantics) ----------
__global__ __launch_bounds__(256) void topk_kernel(
    const float* __restrict__ CLSH, int* __restrict__ ROWSEL,
    float* __restrict__ outIA, float* __restrict__ outIM)
{
    __shared__ float sv[1024];
    __shared__ int   si[1024];
    int seg = blockIdx.x, b = blockIdx.y, t = threadIdx.x;
    int P     = seg ? 1024 : 256;
    int count = seg ? 768  : 255;
    int base  = seg ? 255  : 0;

    for (int e = t; e < P; e += 256) {
        if (e < count) {
            float s = 0.f;
            #pragma unroll
            for (int hh = 0; hh < 12; hh++)
                s += CLSH[(size_t)(b*12 + hh) * 1023 + base + e];
            sv[e] = s;
            si[e] = e;
        } else { sv[e] = -3.4e38f; si[e] = 0x7FFFFFFF; }
    }

    for (int k = 2; k <= P; k <<= 1)
        for (int j = k >> 1; j > 0; j >>= 1) {
            __syncthreads();
            for (int i = t; i < P; i += 256) {
                int ixj = i ^ j;
                if (ixj > i) {
                    float v1 = sv[i], v2 = sv[ixj];
                    int a1 = si[i], a2 = si[ixj];
                    bool before12 = (v1 > v2) || (v1 == v2 && a1 < a2);
                    bool up = ((i & k) == 0);
                    if (up != before12) {
                        sv[i] = v2; sv[ixj] = v1; si[i] = a2; si[ixj] = a1;
                    }
                }
            }
        }
    __syncthreads();

    if (seg == 0) {
        if (t < 128) {
            int idx = si[t];
            if (outIA) outIA[b*128 + t] = (float)idx;
            ROWSEL[b*513 + 1 + t] = b*1024 + 1 + idx;
        }
        if (t == 0) ROWSEL[b*513] = b*1024;
    } else {
        for (int e = t; e < 384; e += 256) {
            int idx = si[e];
            if (outIM) outIM[b*384 + e] = (float)idx;
            ROWSEL[b*513 + 129 + e] = b*1024 + 256 + idx;
        }
    }
}

__global__ void fill_ones(float* __restrict__ p, int n) {
    int i = blockIdx.x * 256 + threadIdx.x;
    if (i < n) p[i] = 1.0f;
}

// ---------------- launcher ----------------
extern "C" void kernel_launch(void* const* d_in, const int* in_sizes, int n_in,
                              void* d_out, int out_size)
{
    const float* x      = (const float*)d_in[0];
    const float* amask  = (const float*)d_in[1];
    const float* w_qkv  = (const float*)d_in[4];
    const float* w_proj = (const float*)d_in[5];
    const float* b_proj = (const float*)d_in[6];
    const float* g1     = (const float*)d_in[7];
    const float* b1     = (const float*)d_in[8];
    const float* g2     = (const float*)d_in[9];
    const float* b2     = (const float*)d_in[10];
    const float* w_fc1  = (const float*)d_in[11];
    const float* b_fc1  = (const float*)d_in[12];
    const float* w_fc2  = (const float*)d_in[13];
    const float* b_fc2  = (const float*)d_in[14];
    float* out = (float*)d_out;

    float *XN, *QKV, *QG, *XATT, *CLSH, *XP, *XN2, *HB; int* ROWSEL;
    cudaGetSymbolAddress((void**)&XN,   g_XN);
    cudaGetSymbolAddress((void**)&QKV,  g_QKV);
    cudaGetSymbolAddress((void**)&QG,   g_QG);
    cudaGetSymbolAddress((void**)&XATT, g_XATT);
    cudaGetSymbolAddress((void**)&CLSH, g_CLSH);
    cudaGetSymbolAddress((void**)&XP,   g_XP);
    cudaGetSymbolAddress((void**)&XN2,  g_XN2);
    cudaGetSymbolAddress((void**)&HB,   g_HB);
    cudaGetSymbolAddress((void**)&ROWSEL, g_ROWSEL);

    const int ATTN_SMEM = (32*1024 + 64*36 + 8448) * 4;  // 174080 B
    cudaFuncSetAttribute(attn_sel_kernel,
        cudaFuncAttributeMaxDynamicSharedMemorySize, ATTN_SMEM);

    const int OFF_IA = 8*513*768;
    const int OFF_IM = OFF_IA + 8*128;
    const int OFF_MK = OFF_IM + 8*384;
    const int MK_SZ  = 8*513*513;
    const int TOTAL  = OFF_MK + MK_SZ;
    float* outIA = (out_size >= TOTAL) ? out + OFF_IA : nullptr;
    float* outIM = (out_size >= TOTAL) ? out + OFF_IM : nullptr;

    // 1. LN1 (all rows)
    ln_kernel<<<B_*N_, 256>>>(x, g1, b1, XN);
    // 2a. K GEMM (fp32 EXACT — feeds cls scores -> top-k). Same column-block
    //     decomposition as R10 => bit-identical K.
    sgemm2<false><<<dim3(6, 64), 256>>>(
        XN, C_, w_qkv + 768, 3*C_, QKV + 768, 3*C_, B_*N_, C_, C_, nullptr);
    // 2b. V GEMM (bf16x3 mma — feeds AV only, tolerant)
    bf_gemm<false,false,0><<<dim3(6, 64), 256>>>(
        XN, C_, w_qkv + 1536, 3*C_, QKV + 1536, 3*C_, B_*N_, C_, C_,
        nullptr, nullptr, nullptr);
    // 3. cls attention row (fp32) -> CLSH
    cls_kernel<<<dim3(H_, B_), 256>>>(XN, w_qkv, QKV, amask, CLSH);
    // 4. top-k -> ROWSEL + idx outputs
    topk_kernel<<<dim3(2, B_), 256>>>(CLSH, ROWSEL, outIA, outIM);
    // 5. gathered Q GEMM (bf16x3): QG = XN[sel] @ w_qkv[:,0:768]
    bf_gemm<true,false,0><<<dim3(6, 33), 256>>>(
        XN, C_, w_qkv, 3*C_, QG, C_, MROWS, C_, C_, nullptr, nullptr, ROWSEL);
    // 6. attention for selected rows only (fp32 SIMT)
    attn_sel_kernel<<<dim3((RN_+31)/32, H_, B_), 256, ATTN_SMEM>>>(
        QG, QKV, amask, ROWSEL, XATT);
    // 7. proj (bf16x3): XP = x[sel] + (XATT @ w_proj + b_proj)
    bf_gemm<false,true,1><<<dim3(6, 33), 256>>>(
        XATT, C_, w_proj, C_, XP, C_, MROWS, C_, C_, b_proj, x, ROWSEL);
    // 8. LN2
    ln_kernel<<<MROWS, 256>>>(XP, g2, b2, XN2);
    // 9. fc1 + GELU (bf16x3)
    bf_gemm<false,false,2><<<dim3(24, 33), 256>>>(
        XN2, C_, w_fc1, HID_, HB, HID_, MROWS, HID_, C_, b_fc1, nullptr, nullptr);
    // 10. fc2 + bias + residual -> d_out (bf16x3)
    bf_gemm<false,false,1><<<dim3(6, 33), 256>>>(
        HB, HID_, w_fc2, C_, out, C_, MROWS, C_, HID_, b_fc2, XP, nullptr);
    // 11. new_mask == all ones (proved in R4)
    if (out_size >= TOTAL)
        fill_ones<<<(MK_SZ + 255)/256, 256>>>(out + OFF_MK, MK_SZ);
}

// round 15
// speedup vs baseline: 1.0036x; 1.0036x over previous
#include <cuda_runtime.h>
#include <cuda_bf16.h>
#include <cstdint>
#include <math.h>

#define B_   8
#define N_   1024
#define C_   768
#define H_   12
#define HID_ 3072
#define RN_  513
#define MROWS (B_*RN_)   // 4104

// ---------------- scratch (static __device__, no allocation) ----------------
__device__ float g_XN  [B_*N_*C_];
__device__ float g_QKV [B_*N_*3*C_];   // K,V region (cols 768..2303) used
__device__ float g_QG  [MROWS*C_];
__device__ float g_XATT[MROWS*C_];
__device__ float g_CLSH[B_*H_*(N_-1)];
__device__ int   g_ROWSEL[B_*RN_];
__device__ float g_XP  [MROWS*C_];
__device__ float g_XN2 [MROWS*C_];
__device__ float g_HB  [MROWS*HID_];

__device__ __forceinline__ float gelu_exact(float v) {
    return 0.5f * v * (1.0f + erff(v * 0.70710678118654752f));
}

// ---------------- LayerNorm (1 row / block, C=768, 256 threads) -------------
__global__ __launch_bounds__(256) void ln_kernel(
    const float* __restrict__ X, const float* __restrict__ g,
    const float* __restrict__ bt, float* __restrict__ Y)
{
    __shared__ float red[8];
    int row = blockIdx.x, t = threadIdx.x;
    const float* xr = X + (size_t)row * C_;
    float x0 = xr[t], x1 = xr[t+256], x2 = xr[t+512];
    float s = x0 + x1 + x2;
    #pragma unroll
    for (int o = 16; o; o >>= 1) s += __shfl_xor_sync(~0u, s, o);
    if ((t & 31) == 0) red[t >> 5] = s;
    __syncthreads();
    float tot = 0.f;
    #pragma unroll
    for (int i = 0; i < 8; i++) tot += red[i];
    float mean = tot * (1.0f/768.0f);
    __syncthreads();
    float d0 = x0-mean, d1 = x1-mean, d2 = x2-mean;
    float q = d0*d0 + d1*d1 + d2*d2;
    #pragma unroll
    for (int o = 16; o; o >>= 1) q += __shfl_xor_sync(~0u, q, o);
    if ((t & 31) == 0) red[t >> 5] = q;
    __syncthreads();
    float tq = 0.f;
    #pragma unroll
    for (int i = 0; i < 8; i++) tq += red[i];
    float rstd = 1.0f / sqrtf(tq * (1.0f/768.0f) + 1e-5f);
    float* yr = Y + (size_t)row * C_;
    yr[t]     = d0*rstd*g[t]     + bt[t];
    yr[t+256] = d1*rstd*g[t+256] + bt[t+256];
    yr[t+512] = d2*rstd*g[t+512] + bt[t+512];
}

// ------- fp32 SGEMM w/ strides (exact path for K): 128x128x8, 8x8 ----------
template<bool GATHER>
__global__ __launch_bounds__(256) void sgemm2(
    const float* __restrict__ A, int lda,
    const float* __restrict__ Bm, int ldb,
    float* __restrict__ Cm, int ldc,
    int M, int N, int K, const int* __restrict__ rowmap)
{
    __shared__ float As[8][128];
    __shared__ float Bs[8][128];
    int t = threadIdx.x;
    int row0 = blockIdx.y * 128, col0 = blockIdx.x * 128;

    int la_r = t >> 1, la_k = (t & 1) * 4;
    long a_base = -1;
    {
        int arow = row0 + la_r;
        if (arow < M) a_base = (long)(GATHER ? rowmap[arow] : arow) * lda;
    }
    int lb_k = t >> 5, lb_c = (t & 31) * 4;
    const float* bp = Bm + (size_t)lb_k * ldb + col0 + lb_c;

    int ty = t >> 4, tx = t & 15;
    float acc[8][8] = {{0.f}};

    float4 av = make_float4(0.f,0.f,0.f,0.f), bv;
    if (a_base >= 0) av = *(const float4*)(A + a_base + la_k);
    bv = *(const float4*)bp;

    for (int k0 = 0; k0 < K; k0 += 8) {
        __syncthreads();
        As[la_k  ][la_r] = av.x;  As[la_k+1][la_r] = av.y;
        As[la_k+2][la_r] = av.z;  As[la_k+3][la_r] = av.w;
        *(float4*)&Bs[lb_k][lb_c] = bv;
        __syncthreads();
        if (k0 + 8 < K) {
            if (a_base >= 0) av = *(const float4*)(A + a_base + k0 + 8 + la_k);
            bv = *(const float4*)(bp + (size_t)(k0 + 8) * ldb);
        }
        #pragma unroll
        for (int kk = 0; kk < 8; kk++) {
            float4 a0 = *(const float4*)&As[kk][ty*8];
            float4 a1 = *(const float4*)&As[kk][ty*8+4];
            float4 b0 = *(const float4*)&Bs[kk][tx*8];
            float4 b1 = *(const float4*)&Bs[kk][tx*8+4];
            float ar[8] = {a0.x,a0.y,a0.z,a0.w,a1.x,a1.y,a1.z,a1.w};
            float br[8] = {b0.x,b0.y,b0.z,b0.w,b1.x,b1.y,b1.z,b1.w};
            #pragma unroll
            for (int i = 0; i < 8; i++)
                #pragma unroll
                for (int j = 0; j < 8; j++)
                    acc[i][j] = fmaf(ar[i], br[j], acc[i][j]);
        }
    }

    #pragma unroll
    for (int i = 0; i < 8; i++) {
        int row = row0 + ty*8 + i;
        if (row < M) {
            #pragma unroll
            for (int jj = 0; jj < 8; jj += 4) {
                int col = col0 + tx*8 + jj;
                float4 v = make_float4(acc[i][jj], acc[i][jj+1], acc[i][jj+2], acc[i][jj+3]);
                *(float4*)&Cm[(size_t)row * ldc + col] = v;
            }
        }
    }
}

// ============ bf16x3 MMA GEMM (m16n8k16 + ldmatrix), 128x128, BK=32 =========
// 8 warps 2(M)x4(N), warp tile 64x32. Error ~2^-17 (post-topk path only).
// EPI: 0 plain, 1 +bias+resid, 2 +bias+GELU. GA: gather A rows; GR: gather resid.
#define LDSM_X4(r0,r1,r2,r3,addr) \
    asm volatile("ldmatrix.sync.aligned.m8n8.x4.shared.b16 {%0,%1,%2,%3},[%4];" \
        : "=r"(r0),"=r"(r1),"=r"(r2),"=r"(r3) : "r"(addr))
#define LDSM_X4T(r0,r1,r2,r3,addr) \
    asm volatile("ldmatrix.sync.aligned.m8n8.x4.trans.shared.b16 {%0,%1,%2,%3},[%4];" \
        : "=r"(r0),"=r"(r1),"=r"(r2),"=r"(r3) : "r"(addr))

__device__ __forceinline__ void mma_bf16(float* c, const uint32_t* a,
                                         uint32_t b0, uint32_t b1) {
    asm volatile(
        "mma.sync.aligned.m16n8k16.row.col.f32.bf16.bf16.f32 "
        "{%0,%1,%2,%3},{%4,%5,%6,%7},{%8,%9},{%0,%1,%2,%3};"
        : "+f"(c[0]), "+f"(c[1]), "+f"(c[2]), "+f"(c[3])
        : "r"(a[0]), "r"(a[1]), "r"(a[2]), "r"(a[3]), "r"(b0), "r"(b1));
}

__device__ __forceinline__ void cvt16(const float* v, uint32_t* uh, uint32_t* ul) {
    #pragma unroll
    for (int p = 0; p < 8; p++) {
        float a = v[2*p], b = v[2*p+1];
        __nv_bfloat16 ha = __float2bfloat16(a), hb = __float2bfloat16(b);
        __nv_bfloat162 hi2; hi2.x = ha; hi2.y = hb;
        __nv_bfloat162 lo2 = __floats2bfloat162_rn(
            a - __bfloat162float(ha), b - __bfloat162float(hb));
        uh[p] = *(uint32_t*)&hi2;
        ul[p] = *(uint32_t*)&lo2;
    }
}

// smem: A rows 128, stride 80B (64B data + 16 pad); B rows 32 (k), stride 272B
#define A_STR 80
#define B_STR 272

template<bool GA, bool GR, int EPI>
__global__ __launch_bounds__(256) void bf_gemm(
    const float* __restrict__ A, int lda,
    const float* __restrict__ Bm, int ldb,
    float* __restrict__ Cm, int ldc,
    int M, int N, int K,
    const float* __restrict__ bias, const float* __restrict__ resid,
    const int* __restrict__ rowmap)
{
    __shared__ __align__(16) char sAh[128*A_STR];
    __shared__ __align__(16) char sAl[128*A_STR];
    __shared__ __align__(16) char sBh[32*B_STR];
    __shared__ __align__(16) char sBl[32*B_STR];

    const int t = threadIdx.x;
    const int lane = t & 31, wid = t >> 5;
    const int lq = lane >> 2, lr = lane & 3;
    const int wm = wid & 1,  wn = wid >> 1;
    const int row0 = blockIdx.y * 128, col0 = blockIdx.x * 128;

    // ---- loader mapping
    const int la_r = t >> 1, la_half = (t & 1);       // A: row, k-half(16)
    const int lb_k = t >> 3, lb_n = (t & 7) * 16;     // B: k-row, n-offset
    long a_base = -1;
    {
        int arow = row0 + la_r;
        if (arow < M) a_base = (long)(GA ? rowmap[arow] : arow) * lda;
    }
    const float* bptr = Bm + (size_t)lb_k * ldb + col0 + lb_n;

    // ---- ldmatrix per-thread addresses
    uint32_t a_h_base, a_l_base, b_h_base, b_l_base;
    {
        uint32_t sa;
        asm("{ .reg .u64 tt; cvta.to.shared.u64 tt, %1; cvt.u32.u64 %0, tt; }"
            : "=r"(sa) : "l"((void*)sAh));
        uint32_t arow = wm*64 + ((lane>>3)&1)*8 + (lane&7);
        uint32_t aoff = arow*A_STR + (lane>>4)*16;
        a_h_base = sa + aoff;
        asm("{ .reg .u64 tt; cvta.to.shared.u64 tt, %1; cvt.u32.u64 %0, tt; }"
            : "=r"(sa) : "l"((void*)sAl));
        a_l_base = sa + aoff;
        uint32_t brow = ((lane>>3)&1)*8 + (lane&7);
        uint32_t boff = brow*B_STR + wn*64 + (lane>>4)*16;
        asm("{ .reg .u64 tt; cvta.to.shared.u64 tt, %1; cvt.u32.u64 %0, tt; }"
            : "=r"(sa) : "l"((void*)sBh));
        b_h_base = sa + boff;
        asm("{ .reg .u64 tt; cvta.to.shared.u64 tt, %1; cvt.u32.u64 %0, tt; }"
            : "=r"(sa) : "l"((void*)sBl));
        b_l_base = sa + boff;
    }

    float acc[4][4][4];
    #pragma unroll
    for (int i = 0; i < 4; i++)
        #pragma unroll
        for (int j = 0; j < 4; j++)
            #pragma unroll
            for (int q = 0; q < 4; q++) acc[i][j][q] = 0.f;

    float av[16], bv[16];
    auto ldg = [&](int kt) {
        int k0 = kt * 32 + la_half * 16;
        if (a_base >= 0) {
            #pragma unroll
            for (int j = 0; j < 4; j++)
                *(float4*)&av[j*4] = *(const float4*)(A + a_base + k0 + j*4);
        } else {
            #pragma unroll
            for (int j = 0; j < 16; j++) av[j] = 0.f;
        }
        const float* bp = bptr + (size_t)(kt*32) * ldb;
        #pragma unroll
        for (int j = 0; j < 4; j++)
            *(float4*)&bv[j*4] = *(const float4*)(bp + j*4);
    };

    const int KT = K >> 5;
    ldg(0);

    for (int kt = 0; kt < KT; ++kt) {
        // store current tile (hi/lo split) to smem
        {
            uint32_t uh[8], ul[8];
            cvt16(av, uh, ul);
            char* pa = sAh + la_r*A_STR + la_half*32;
            *(uint4*)pa        = make_uint4(uh[0],uh[1],uh[2],uh[3]);
            *(uint4*)(pa + 16) = make_uint4(uh[4],uh[5],uh[6],uh[7]);
            pa = sAl + la_r*A_STR + la_half*32;
            *(uint4*)pa        = make_uint4(ul[0],ul[1],ul[2],ul[3]);
            *(uint4*)(pa + 16) = make_uint4(ul[4],ul[5],ul[6],ul[7]);
            cvt16(bv, uh, ul);
            char* pb = sBh + lb_k*B_STR + lb_n*2;
            *(uint4*)pb        = make_uint4(uh[0],uh[1],uh[2],uh[3]);
            *(uint4*)(pb + 16) = make_uint4(uh[4],uh[5],uh[6],uh[7]);
            pb = sBl + lb_k*B_STR + lb_n*2;
            *(uint4*)pb        = make_uint4(ul[0],ul[1],ul[2],ul[3]);
            *(uint4*)(pb + 16) = make_uint4(ul[4],ul[5],ul[6],ul[7]);
        }
        __syncthreads();
        if (kt + 1 < KT) ldg(kt + 1);

        #pragma unroll
        for (int ks = 0; ks < 2; ks++) {
            uint32_t ah[4][4], al_[4][4], bh[4][2], bl_[4][2];
            #pragma unroll
            for (int mf = 0; mf < 4; mf++) {
                uint32_t aa = a_h_base + mf*(16*A_STR) + ks*32;
                LDSM_X4(ah[mf][0],ah[mf][1],ah[mf][2],ah[mf][3], aa);
                aa = a_l_base + mf*(16*A_STR) + ks*32;
                LDSM_X4(al_[mf][0],al_[mf][1],al_[mf][2],al_[mf][3], aa);
            }
            #pragma unroll
            for (int nfp = 0; nfp < 2; nfp++) {
                uint32_t bb = b_h_base + ks*(16*B_STR) + nfp*32;
                LDSM_X4T(bh[2*nfp][0], bh[2*nfp][1], bh[2*nfp+1][0], bh[2*nfp+1][1], bb);
                bb = b_l_base + ks*(16*B_STR) + nfp*32;
                LDSM_X4T(bl_[2*nfp][0], bl_[2*nfp][1], bl_[2*nfp+1][0], bl_[2*nfp+1][1], bb);
            }
            #pragma unroll
            for (int mf = 0; mf < 4; mf++)
                #pragma unroll
                for (int nf = 0; nf < 4; nf++) {
                    float* c = acc[mf][nf];
                    mma_bf16(c, ah[mf],  bh[nf][0],  bh[nf][1]);
                    mma_bf16(c, ah[mf],  bl_[nf][0], bl_[nf][1]);
                    mma_bf16(c, al_[mf], bh[nf][0],  bh[nf][1]);
                }
        }
        __syncthreads();
    }

    // ---- epilogue (same fragment layout as m16n8 tf32 version)
    #pragma unroll
    for (int mf = 0; mf < 4; mf++) {
        int rbase = row0 + wm*64 + mf*16 + lq;
        #pragma unroll
        for (int half = 0; half < 2; half++) {
            int row = rbase + half*8;
            if (row < M) {
                long rres = 0;
                if (EPI == 1) rres = (long)(GR ? rowmap[row] : row) * N;
                #pragma unroll
                for (int nf = 0; nf < 4; nf++) {
                    int col = col0 + wn*32 + nf*8 + lr*2;
                    float v0 = acc[mf][nf][half*2+0];
                    float v1 = acc[mf][nf][half*2+1];
                    if (EPI != 0) { v0 += bias[col]; v1 += bias[col+1]; }
                    if (EPI == 2) { v0 = gelu_exact(v0); v1 = gelu_exact(v1); }
                    if (EPI == 1) { v0 += resid[rres+col]; v1 += resid[rres+col+1]; }
                    *(float2*)&Cm[(size_t)row * ldc + col] = make_float2(v0, v1);
                }
            }
        }
    }
}

// ------------- cls attention row (q0 = xn0 @ Wq, softmax, -> CLSH) ----------
__global__ __launch_bounds__(256) void cls_kernel(
    const float* __restrict__ XN, const float* __restrict__ wqkv,
    const float* __restrict__ QKV, const float* __restrict__ amask,
    float* __restrict__ CLSH)
{
    __shared__ float q0[64];
    __shared__ float sS[1024];
    __shared__ float red[8];
    int h = blockIdx.x, b = blockIdx.y, t = threadIdx.x;

    {
        int d = t >> 2, part = t & 3;
        const float* xr = XN + (size_t)b * N_ * C_;
        const float* wc = wqkv + h*64 + d;
        float s = 0.f;
        int k0 = part * 192;
        for (int k = k0; k < k0 + 192; k++)
            s = fmaf(xr[k], wc[(size_t)k * 2304], s);
        s += __shfl_xor_sync(~0u, s, 1);
        s += __shfl_xor_sync(~0u, s, 2);
        if (part == 0) q0[d] = s;
    }
    __syncthreads();

    float sv[4];
    #pragma unroll
    for (int j = 0; j < 4; j++) {
        int m = t + 256*j;
        const float* kr = QKV + (size_t)(b*N_ + m)*2304 + 768 + h*64;
        float acc = 0.f;
        #pragma unroll
        for (int d = 0; d < 64; d++) acc = fmaf(q0[d], kr[d], acc);
        sv[j] = acc * 0.125f;
    }
    float mx = fmaxf(fmaxf(sv[0], sv[1]), fmaxf(sv[2], sv[3]));
    #pragma unroll
    for (int o = 16; o; o >>= 1) mx = fmaxf(mx, __shfl_xor_sync(~0u, mx, o));
    if ((t & 31) == 0) red[t >> 5] = mx;
    __syncthreads();
    mx = red[0];
    #pragma unroll
    for (int i = 1; i < 8; i++) mx = fmaxf(mx, red[i]);

    const float* mrow = amask + (size_t)b * N_ * N_;
    float sum = 0.f;
    #pragma unroll
    for (int j = 0; j < 4; j++) {
        int m = t + 256*j;
        float e = expf(sv[j] - mx) * mrow[m];
        sS[m] = e;
        sum += e;
    }
    #pragma unroll
    for (int o = 16; o; o >>= 1) sum += __shfl_xor_sync(~0u, sum, o);
    __syncthreads();
    if ((t & 31) == 0) red[t >> 5] = sum;
    __syncthreads();
    sum = 0.f;
    #pragma unroll
    for (int i = 0; i < 8; i++) sum += red[i];
    float rinv = 1.0f / (sum + 1e-6f);
    const float epsn = 1e-6f / 1024.0f;
    float* cl = CLSH + (size_t)(b*H_ + h) * (N_ - 1);
    #pragma unroll
    for (int j = 0; j < 4; j++) {
        int m = t + 256*j;
        if (m >= 1) cl[m-1] = (sS[m] + epsn) * rinv;
    }
}

// --------- Attention for SELECTED rows: block = (32 compact rows, h, b) -----
__global__ __launch_bounds__(256) void attn_sel_kernel(
    const float* __restrict__ QG, const float* __restrict__ QKV,
    const float* __restrict__ amask, const int* __restrict__ ROWSEL,
    float* __restrict__ XATT)
{
    extern __shared__ float smx[];
    float* sS  = smx;                 // 32*1024
    float* sQt = smx + 32*1024;       // [64][36]
    float* sT  = sQt + 64*36;         // 8448 floats
    int t = threadIdx.x;
    int n0 = blockIdx.x * 32, h = blockIdx.y, b = blockIdx.z;
    size_t base_bh = (size_t)b * N_ * 2304 + (size_t)h * 64;

    for (int e = t; e < 32*64; e += 256) {
        int i = e >> 6, d = e & 63;
        int r = n0 + i;
        sQt[d*36 + i] = (r < RN_)
            ? QG[(size_t)(b*RN_ + r) * C_ + h*64 + d] : 0.f;
    }

    int ty = t >> 5, tx = t & 31;

    for (int kt = 0; kt < 8; kt++) {
        int m0 = kt << 7;
        __syncthreads();
        for (int e = t; e < 128*64; e += 256) {
            int m = e >> 6, d = e & 63;
            sT[d*132 + m] = QKV[base_bh + 768 + (size_t)(m0 + m) * 2304 + d];
        }
        __syncthreads();
        float acc[4][4] = {{0.f}};
        #pragma unroll 4
        for (int d = 0; d < 64; d++) {
            float4 aq = *(const float4*)&sQt[d*36 + ty*4];
            float4 bk = *(const float4*)&sT[d*132 + tx*4];
            float ar[4] = {aq.x,aq.y,aq.z,aq.w};
            float br[4] = {bk.x,bk.y,bk.z,bk.w};
            #pragma unroll
            for (int i = 0; i < 4; i++)
                #pragma unroll
                for (int j = 0; j < 4; j++)
                    acc[i][j] = fmaf(ar[i], br[j], acc[i][j]);
        }
        #pragma unroll
        for (int i = 0; i < 4; i++) {
            float4 v = make_float4(acc[i][0]*0.125f, acc[i][1]*0.125f,
                                   acc[i][2]*0.125f, acc[i][3]*0.125f);
            *(float4*)&sS[(ty*4+i)*1024 + m0 + tx*4] = v;
        }
    }
    __syncthreads();

    int lane = t & 31, w = t >> 5;
    for (int rr = 0; rr < 4; rr++) {
        int i = w + rr*8;
        int r = n0 + i;
        if (r >= RN_) continue;
        int norig = ROWSEL[b*RN_ + r] - b*1024;
        float* row = sS + i*1024;
        float mx = -3.4e38f;
        for (int m = lane; m < 1024; m += 32) mx = fmaxf(mx, row[m]);
        #pragma unroll
        for (int o = 16; o; o >>= 1) mx = fmaxf(mx, __shfl_xor_sync(~0u, mx, o));
        const float* mrow = amask + (size_t)(b * N_ + norig) * N_;
        float sum = 0.f;
        for (int m = lane; m < 1024; m += 32) {
            float e = expf(row[m] - mx) * mrow[m];
            row[m] = e;
            sum += e;
        }
        #pragma unroll
        for (int o = 16; o; o >>= 1) sum += __shfl_xor_sync(~0u, sum, o);
        float rinv = 1.0f / (sum + 1e-6f);
        const float epsn = 1e-6f / 1024.0f;
        for (int m = lane; m < 1024; m += 32) row[m] = (row[m] + epsn) * rinv;
    }
    __syncthreads();

    float oacc[4][2] = {{0.f}};
    for (int vt = 0; vt < 8; vt++) {
        int m0 = vt << 7;
        __syncthreads();
        for (int e = t; e < 128*64; e += 256) {
            int m = e >> 6, d = e & 63;
            sT[m*66 + d] = QKV[base_bh + 1536 + (size_t)(m0 + m) * 2304 + d];
        }
        __syncthreads();
        #pragma unroll 4
        for (int m = 0; m < 128; m++) {
            float2 vv = *(const float2*)&sT[m*66 + tx*2];
            #pragma unroll
            for (int i = 0; i < 4; i++) {
                float a = sS[(ty*4+i)*1024 + m0 + m];
                oacc[i][0] = fmaf(a, vv.x, oacc[i][0]);
                oacc[i][1] = fmaf(a, vv.y, oacc[i][1]);
            }
        }
    }
    #pragma unroll
    for (int i = 0; i < 4; i++) {
        int r = n0 + ty*4 + i;
        if (r < RN_) {
            float2 o2 = make_float2(oacc[i][0], oacc[i][1]);
            *(float2*)&XATT[(size_t)(b*RN_ + r) * C_ + h*64 + tx*2] = o2;
        }
    }
}

// ---------------- top-k via bitonic sort (jax.lax.top_k semantics) ----------
__global__ __launch_bounds__(256) void topk_kernel(
    const float* __restrict__ CLSH, int* __restrict__ ROWSEL,
    float* __restrict__ outIA, float* __restrict__ outIM)
{
    __shared__ float sv[1024];
    __shared__ int   si[1024];
    int seg = blockIdx.x, b = blockIdx.y, t = threadIdx.x;
    int P     = seg ? 1024 : 256;
    int count = seg ? 768  : 255;
    int base  = seg ? 255  : 0;

    for (int e = t; e < P; e += 256) {
        if (e < count) {
            float s = 0.f;
            #pragma unroll
            for (int hh = 0; hh < 12; hh++)
                s += CLSH[(size_t)(b*12 + hh) * 1023 + base + e];
            sv[e] = s;
            si[e] = e;
        } else { sv[e] = -3.4e38f; si[e] = 0x7FFFFFFF; }
    }

    for (int k = 2; k <= P; k <<= 1)
        for (int j = k >> 1; j > 0; j >>= 1) {
            __syncthreads();
            for (int i = t; i < P; i += 256) {
                int ixj = i ^ j;
                if (ixj > i) {
                    float v1 = sv[i], v2 = sv[ixj];
                    int a1 = si[i], a2 = si[ixj];
                    bool before12 = (v1 > v2) || (v1 == v2 && a1 < a2);
                    bool up = ((i & k) == 0);
                    if (up != before12) {
                        sv[i] = v2; sv[ixj] = v1; si[i] = a2; si[ixj] = a1;
                    }
                }
            }
        }
    __syncthreads();

    if (seg == 0) {
        if (t < 128) {
            int idx = si[t];
            if (outIA) outIA[b*128 + t] = (float)idx;
            ROWSEL[b*513 + 1 + t] = b*1024 + 1 + idx;
        }
        if (t == 0) ROWSEL[b*513] = b*1024;
    } else {
        for (int e = t; e < 384; e += 256) {
            int idx = si[e];
            if (outIM) outIM[b*384 + e] = (float)idx;
            ROWSEL[b*513 + 129 + e] = b*1024 + 256 + idx;
        }
    }
}

__global__ void fill_ones(float* __restrict__ p, int n) {
    int i = blockIdx.x * 256 + threadIdx.x;
    if (i < n) p[i] = 1.0f;
}

// ---------------- launcher ----------------
extern "C" void kernel_launch(void* const* d_in, const int* in_sizes, int n_in,
                              void* d_out, int out_size)
{
    const float* x      = (const float*)d_in[0];
    const float* amask  = (const float*)d_in[1];
    const float* w_qkv  = (const float*)d_in[4];
    const float* w_proj = (const float*)d_in[5];
    const float* b_proj = (const float*)d_in[6];
    const float* g1     = (const float*)d_in[7];
    const float* b1     = (const float*)d_in[8];
    const float* g2     = (const float*)d_in[9];
    const float* b2     = (const float*)d_in[10];
    const float* w_fc1  = (const float*)d_in[11];
    const float* b_fc1  = (const float*)d_in[12];
    const float* w_fc2  = (const float*)d_in[13];
    const float* b_fc2  = (const float*)d_in[14];
    float* out = (float*)d_out;

    float *XN, *QKV, *QG, *XATT, *CLSH, *XP, *XN2, *HB; int* ROWSEL;
    cudaGetSymbolAddress((void**)&XN,   g_XN);
    cudaGetSymbolAddress((void**)&QKV,  g_QKV);
    cudaGetSymbolAddress((void**)&QG,   g_QG);
    cudaGetSymbolAddress((void**)&XATT, g_XATT);
    cudaGetSymbolAddress((void**)&CLSH, g_CLSH);
    cudaGetSymbolAddress((void**)&XP,   g_XP);
    cudaGetSymbolAddress((void**)&XN2,  g_XN2);
    cudaGetSymbolAddress((void**)&HB,   g_HB);
    cudaGetSymbolAddress((void**)&ROWSEL, g_ROWSEL);

    const int ATTN_SMEM = (32*1024 + 64*36 + 8448) * 4;  // 174080 B
    cudaFuncSetAttribute(attn_sel_kernel,
        cudaFuncAttributeMaxDynamicSharedMemorySize, ATTN_SMEM);

    const int OFF_IA = 8*513*768;
    const int OFF_IM = OFF_IA + 8*128;
    const int OFF_MK = OFF_IM + 8*384;
    const int MK_SZ  = 8*513*513;
    const int TOTAL  = OFF_MK + MK_SZ;
    float* outIA = (out_size >= TOTAL) ? out + OFF_IA : nullptr;
    float* outIM = (out_size >= TOTAL) ? out + OFF_IM : nullptr;

    // 1. LN1 (all rows)
    ln_kernel<<<B_*N_, 256>>>(x, g1, b1, XN);
    // 2a. K GEMM (fp32 EXACT — feeds cls scores -> top-k). Same column-block
    //     decomposition as R10 => bit-identical K.
    sgemm2<false><<<dim3(6, 64), 256>>>(
        XN, C_, w_qkv + 768, 3*C_, QKV + 768, 3*C_, B_*N_, C_, C_, nullptr);
    // 2b. V GEMM (bf16x3 mma — feeds AV only, tolerant)
    bf_gemm<false,false,0><<<dim3(6, 64), 256>>>(
        XN, C_, w_qkv + 1536, 3*C_, QKV + 1536, 3*C_, B_*N_, C_, C_,
        nullptr, nullptr, nullptr);
    // 3. cls attention row (fp32) -> CLSH
    cls_kernel<<<dim3(H_, B_), 256>>>(XN, w_qkv, QKV, amask, CLSH);
    // 4. top-k -> ROWSEL + idx outputs
    topk_kernel<<<dim3(2, B_), 256>>>(CLSH, ROWSEL, outIA, outIM);
    // 5. gathered Q GEMM (bf16x3): QG = XN[sel] @ w_qkv[:,0:768]
    bf_gemm<true,false,0><<<dim3(6, 33), 256>>>(
        XN, C_, w_qkv, 3*C_, QG, C_, MROWS, C_, C_, nullptr, nullptr, ROWSEL);
    // 6. attention for selected rows only (fp32 SIMT)
    attn_sel_kernel<<<dim3((RN_+31)/32, H_, B_), 256, ATTN_SMEM>>>(
        QG, QKV, amask, ROWSEL, XATT);
    // 7. proj (bf16x3): XP = x[sel] + (XATT @ w_proj + b_proj)
    bf_gemm<false,true,1><<<dim3(6, 33), 256>>>(
        XATT, C_, w_proj, C_, XP, C_, MROWS, C_, C_, b_proj, x, ROWSEL);
    // 8. LN2
    ln_kernel<<<MROWS, 256>>>(XP, g2, b2, XN2);
    // 9. fc1 + GELU (bf16x3)
    bf_gemm<false,false,2><<<dim3(24, 33), 256>>>(
        XN2, C_, w_fc1, HID_, HB, HID_, MROWS, HID_, C_, b_fc1, nullptr, nullptr);
    // 10. fc2 + bias + residual -> d_out (bf16x3)
    bf_gemm<false,false,1><<<dim3(6, 33), 256>>>(
        HB, HID_, w_fc2, C_, out, C_, MROWS, C_, HID_, b_fc2, XP, nullptr);
    // 11. new_mask == all ones (proved in R4)
    if (out_size >= TOTAL)
        fill_ones<<<(MK_SZ + 255)/256, 256>>>(out + OFF_MK, MK_SZ);
}

// round 16
// speedup vs baseline: 1.2977x; 1.2930x over previous
#include <cuda_runtime.h>
#include <cuda_bf16.h>
#include <cstdint>
#include <math.h>

#define B_   8
#define N_   1024
#define C_   768
#define H_   12
#define HID_ 3072
#define RN_  513
#define MROWS (B_*RN_)   // 4104

// ---------------- scratch (static __device__, no allocation) ----------------
__device__ float g_XN  [B_*N_*C_];
__device__ float g_QKV [B_*N_*3*C_];   // K,V region (cols 768..2303) used
__device__ float g_KT  [B_*H_*64*N_];  // K transposed: [b,h,d,m]
__device__ float g_QG  [MROWS*C_];
__device__ float g_XATT[MROWS*C_];
__device__ float g_CLSH[B_*H_*(N_-1)];
__device__ int   g_ROWSEL[B_*RN_];
__device__ float g_XP  [MROWS*C_];
__device__ float g_XN2 [MROWS*C_];
__device__ float g_HB  [MROWS*HID_];

__device__ __forceinline__ float gelu_exact(float v) {
    return 0.5f * v * (1.0f + erff(v * 0.70710678118654752f));
}

// ---------------- LayerNorm (1 row / block, C=768, 256 threads) -------------
__global__ __launch_bounds__(256) void ln_kernel(
    const float* __restrict__ X, const float* __restrict__ g,
    const float* __restrict__ bt, float* __restrict__ Y)
{
    __shared__ float red[8];
    int row = blockIdx.x, t = threadIdx.x;
    const float* xr = X + (size_t)row * C_;
    float x0 = xr[t], x1 = xr[t+256], x2 = xr[t+512];
    float s = x0 + x1 + x2;
    #pragma unroll
    for (int o = 16; o; o >>= 1) s += __shfl_xor_sync(~0u, s, o);
    if ((t & 31) == 0) red[t >> 5] = s;
    __syncthreads();
    float tot = 0.f;
    #pragma unroll
    for (int i = 0; i < 8; i++) tot += red[i];
    float mean = tot * (1.0f/768.0f);
    __syncthreads();
    float d0 = x0-mean, d1 = x1-mean, d2 = x2-mean;
    float q = d0*d0 + d1*d1 + d2*d2;
    #pragma unroll
    for (int o = 16; o; o >>= 1) q += __shfl_xor_sync(~0u, q, o);
    if ((t & 31) == 0) red[t >> 5] = q;
    __syncthreads();
    float tq = 0.f;
    #pragma unroll
    for (int i = 0; i < 8; i++) tq += red[i];
    float rstd = 1.0f / sqrtf(tq * (1.0f/768.0f) + 1e-5f);
    float* yr = Y + (size_t)row * C_;
    yr[t]     = d0*rstd*g[t]     + bt[t];
    yr[t+256] = d1*rstd*g[t+256] + bt[t+256];
    yr[t+512] = d2*rstd*g[t+512] + bt[t+512];
}

// ------- fp32 SGEMM w/ strides (exact path for K): 128x128x8, 8x8 ----------
template<bool GATHER>
__global__ __launch_bounds__(256) void sgemm2(
    const float* __restrict__ A, int lda,
    const float* __restrict__ Bm, int ldb,
    float* __restrict__ Cm, int ldc,
    int M, int N, int K, const int* __restrict__ rowmap)
{
    __shared__ float As[8][128];
    __shared__ float Bs[8][128];
    int t = threadIdx.x;
    int row0 = blockIdx.y * 128, col0 = blockIdx.x * 128;

    int la_r = t >> 1, la_k = (t & 1) * 4;
    long a_base = -1;
    {
        int arow = row0 + la_r;
        if (arow < M) a_base = (long)(GATHER ? rowmap[arow] : arow) * lda;
    }
    int lb_k = t >> 5, lb_c = (t & 31) * 4;
    const float* bp = Bm + (size_t)lb_k * ldb + col0 + lb_c;

    int ty = t >> 4, tx = t & 15;
    float acc[8][8] = {{0.f}};

    float4 av = make_float4(0.f,0.f,0.f,0.f), bv;
    if (a_base >= 0) av = *(const float4*)(A + a_base + la_k);
    bv = *(const float4*)bp;

    for (int k0 = 0; k0 < K; k0 += 8) {
        __syncthreads();
        As[la_k  ][la_r] = av.x;  As[la_k+1][la_r] = av.y;
        As[la_k+2][la_r] = av.z;  As[la_k+3][la_r] = av.w;
        *(float4*)&Bs[lb_k][lb_c] = bv;
        __syncthreads();
        if (k0 + 8 < K) {
            if (a_base >= 0) av = *(const float4*)(A + a_base + k0 + 8 + la_k);
            bv = *(const float4*)(bp + (size_t)(k0 + 8) * ldb);
        }
        #pragma unroll
        for (int kk = 0; kk < 8; kk++) {
            float4 a0 = *(const float4*)&As[kk][ty*8];
            float4 a1 = *(const float4*)&As[kk][ty*8+4];
            float4 b0 = *(const float4*)&Bs[kk][tx*8];
            float4 b1 = *(const float4*)&Bs[kk][tx*8+4];
            float ar[8] = {a0.x,a0.y,a0.z,a0.w,a1.x,a1.y,a1.z,a1.w};
            float br[8] = {b0.x,b0.y,b0.z,b0.w,b1.x,b1.y,b1.z,b1.w};
            #pragma unroll
            for (int i = 0; i < 8; i++)
                #pragma unroll
                for (int j = 0; j < 8; j++)
                    acc[i][j] = fmaf(ar[i], br[j], acc[i][j]);
        }
    }

    #pragma unroll
    for (int i = 0; i < 8; i++) {
        int row = row0 + ty*8 + i;
        if (row < M) {
            #pragma unroll
            for (int jj = 0; jj < 8; jj += 4) {
                int col = col0 + tx*8 + jj;
                float4 v = make_float4(acc[i][jj], acc[i][jj+1], acc[i][jj+2], acc[i][jj+3]);
                *(float4*)&Cm[(size_t)row * ldc + col] = v;
            }
        }
    }
}

// ============ bf16 helpers + mma ============================================
#define LDSM_X4(r0,r1,r2,r3,addr) \
    asm volatile("ldmatrix.sync.aligned.m8n8.x4.shared.b16 {%0,%1,%2,%3},[%4];" \
        : "=r"(r0),"=r"(r1),"=r"(r2),"=r"(r3) : "r"(addr))
#define LDSM_X4T(r0,r1,r2,r3,addr) \
    asm volatile("ldmatrix.sync.aligned.m8n8.x4.trans.shared.b16 {%0,%1,%2,%3},[%4];" \
        : "=r"(r0),"=r"(r1),"=r"(r2),"=r"(r3) : "r"(addr))
#define LDSM_X2T(r0,r1,addr) \
    asm volatile("ldmatrix.sync.aligned.m8n8.x2.trans.shared.b16 {%0,%1},[%2];" \
        : "=r"(r0),"=r"(r1) : "r"(addr))

__device__ __forceinline__ void mma_bf16(float* c, const uint32_t* a,
                                         uint32_t b0, uint32_t b1) {
    asm volatile(
        "mma.sync.aligned.m16n8k16.row.col.f32.bf16.bf16.f32 "
        "{%0,%1,%2,%3},{%4,%5,%6,%7},{%8,%9},{%0,%1,%2,%3};"
        : "+f"(c[0]), "+f"(c[1]), "+f"(c[2]), "+f"(c[3])
        : "r"(a[0]), "r"(a[1]), "r"(a[2]), "r"(a[3]), "r"(b0), "r"(b1));
}

__device__ __forceinline__ void cvt16(const float* v, uint32_t* uh, uint32_t* ul) {
    #pragma unroll
    for (int p = 0; p < 8; p++) {
        float a = v[2*p], b = v[2*p+1];
        __nv_bfloat16 ha = __float2bfloat16(a), hb = __float2bfloat16(b);
        __nv_bfloat162 hi2; hi2.x = ha; hi2.y = hb;
        __nv_bfloat162 lo2 = __floats2bfloat162_rn(
            a - __bfloat162float(ha), b - __bfloat162float(hb));
        uh[p] = *(uint32_t*)&hi2;
        ul[p] = *(uint32_t*)&lo2;
    }
}
__device__ __forceinline__ void cvt8(const float* v, uint32_t* uh, uint32_t* ul) {
    #pragma unroll
    for (int p = 0; p < 4; p++) {
        float a = v[2*p], b = v[2*p+1];
        __nv_bfloat16 ha = __float2bfloat16(a), hb = __float2bfloat16(b);
        __nv_bfloat162 hi2; hi2.x = ha; hi2.y = hb;
        __nv_bfloat162 lo2 = __floats2bfloat162_rn(
            a - __bfloat162float(ha), b - __bfloat162float(hb));
        uh[p] = *(uint32_t*)&hi2;
        ul[p] = *(uint32_t*)&lo2;
    }
}
__device__ __forceinline__ uint32_t smem_u32p(const void* p) {
    uint32_t a;
    asm("{ .reg .u64 t; cvta.to.shared.u64 t, %1; cvt.u32.u64 %0, t; }"
        : "=r"(a) : "l"(p));
    return a;
}

// ============ bf16x3 MMA GEMM (m16n8k16 + ldmatrix), 128x128, BK=32 =========
#define A_STR 80
#define B_STR 272

template<bool GA, bool GR, int EPI>
__global__ __launch_bounds__(256) void bf_gemm(
    const float* __restrict__ A, int lda,
    const float* __restrict__ Bm, int ldb,
    float* __restrict__ Cm, int ldc,
    int M, int N, int K,
    const float* __restrict__ bias, const float* __restrict__ resid,
    const int* __restrict__ rowmap)
{
    __shared__ __align__(16) char sAh[128*A_STR];
    __shared__ __align__(16) char sAl[128*A_STR];
    __shared__ __align__(16) char sBh[32*B_STR];
    __shared__ __align__(16) char sBl[32*B_STR];

    const int t = threadIdx.x;
    const int lane = t & 31, wid = t >> 5;
    const int lq = lane >> 2, lr = lane & 3;
    const int wm = wid & 1,  wn = wid >> 1;
    const int row0 = blockIdx.y * 128, col0 = blockIdx.x * 128;

    const int la_r = t >> 1, la_half = (t & 1);
    const int lb_k = t >> 3, lb_n = (t & 7) * 16;
    long a_base = -1;
    {
        int arow = row0 + la_r;
        if (arow < M) a_base = (long)(GA ? rowmap[arow] : arow) * lda;
    }
    const float* bptr = Bm + (size_t)lb_k * ldb + col0 + lb_n;

    uint32_t a_h_base, a_l_base, b_h_base, b_l_base;
    {
        uint32_t arow = wm*64 + ((lane>>3)&1)*8 + (lane&7);
        uint32_t aoff = arow*A_STR + (lane>>4)*16;
        a_h_base = smem_u32p(sAh) + aoff;
        a_l_base = smem_u32p(sAl) + aoff;
        uint32_t brow = ((lane>>3)&1)*8 + (lane&7);
        uint32_t boff = brow*B_STR + wn*64 + (lane>>4)*16;
        b_h_base = smem_u32p(sBh) + boff;
        b_l_base = smem_u32p(sBl) + boff;
    }

    float acc[4][4][4];
    #pragma unroll
    for (int i = 0; i < 4; i++)
        #pragma unroll
        for (int j = 0; j < 4; j++)
            #pragma unroll
            for (int q = 0; q < 4; q++) acc[i][j][q] = 0.f;

    float av[16], bv[16];
    auto ldg = [&](int kt) {
        int k0 = kt * 32 + la_half * 16;
        if (a_base >= 0) {
            #pragma unroll
            for (int j = 0; j < 4; j++)
                *(float4*)&av[j*4] = *(const float4*)(A + a_base + k0 + j*4);
        } else {
            #pragma unroll
            for (int j = 0; j < 16; j++) av[j] = 0.f;
        }
        const float* bp = bptr + (size_t)(kt*32) * ldb;
        #pragma unroll
        for (int j = 0; j < 4; j++)
            *(float4*)&bv[j*4] = *(const float4*)(bp + j*4);
    };

    const int KT = K >> 5;
    ldg(0);

    for (int kt = 0; kt < KT; ++kt) {
        {
            uint32_t uh[8], ul[8];
            cvt16(av, uh, ul);
            char* pa = sAh + la_r*A_STR + la_half*32;
            *(uint4*)pa        = make_uint4(uh[0],uh[1],uh[2],uh[3]);
            *(uint4*)(pa + 16) = make_uint4(uh[4],uh[5],uh[6],uh[7]);
            pa = sAl + la_r*A_STR + la_half*32;
            *(uint4*)pa        = make_uint4(ul[0],ul[1],ul[2],ul[3]);
            *(uint4*)(pa + 16) = make_uint4(ul[4],ul[5],ul[6],ul[7]);
            cvt16(bv, uh, ul);
            char* pb = sBh + lb_k*B_STR + lb_n*2;
            *(uint4*)pb        = make_uint4(uh[0],uh[1],uh[2],uh[3]);
            *(uint4*)(pb + 16) = make_uint4(uh[4],uh[5],uh[6],uh[7]);
            pb = sBl + lb_k*B_STR + lb_n*2;
            *(uint4*)pb        = make_uint4(ul[0],ul[1],ul[2],ul[3]);
            *(uint4*)(pb + 16) = make_uint4(ul[4],ul[5],ul[6],ul[7]);
        }
        __syncthreads();
        if (kt + 1 < KT) ldg(kt + 1);

        #pragma unroll
        for (int ks = 0; ks < 2; ks++) {
            uint32_t ah[4][4], al_[4][4], bh[4][2], bl_[4][2];
            #pragma unroll
            for (int mf = 0; mf < 4; mf++) {
                uint32_t aa = a_h_base + mf*(16*A_STR) + ks*32;
                LDSM_X4(ah[mf][0],ah[mf][1],ah[mf][2],ah[mf][3], aa);
                aa = a_l_base + mf*(16*A_STR) + ks*32;
                LDSM_X4(al_[mf][0],al_[mf][1],al_[mf][2],al_[mf][3], aa);
            }
            #pragma unroll
            for (int nfp = 0; nfp < 2; nfp++) {
                uint32_t bb = b_h_base + ks*(16*B_STR) + nfp*32;
                LDSM_X4T(bh[2*nfp][0], bh[2*nfp][1], bh[2*nfp+1][0], bh[2*nfp+1][1], bb);
                bb = b_l_base + ks*(16*B_STR) + nfp*32;
                LDSM_X4T(bl_[2*nfp][0], bl_[2*nfp][1], bl_[2*nfp+1][0], bl_[2*nfp+1][1], bb);
            }
            #pragma unroll
            for (int mf = 0; mf < 4; mf++)
                #pragma unroll
                for (int nf = 0; nf < 4; nf++) {
                    float* c = acc[mf][nf];
                    mma_bf16(c, ah[mf],  bh[nf][0],  bh[nf][1]);
                    mma_bf16(c, ah[mf],  bl_[nf][0], bl_[nf][1]);
                    mma_bf16(c, al_[mf], bh[nf][0],  bh[nf][1]);
                }
        }
        __syncthreads();
    }

    #pragma unroll
    for (int mf = 0; mf < 4; mf++) {
        int rbase = row0 + wm*64 + mf*16 + lq;
        #pragma unroll
        for (int half = 0; half < 2; half++) {
            int row = rbase + half*8;
            if (row < M) {
                long rres = 0;
                if (EPI == 1) rres = (long)(GR ? rowmap[row] : row) * N;
                #pragma unroll
                for (int nf = 0; nf < 4; nf++) {
                    int col = col0 + wn*32 + nf*8 + lr*2;
                    float v0 = acc[mf][nf][half*2+0];
                    float v1 = acc[mf][nf][half*2+1];
                    if (EPI != 0) { v0 += bias[col]; v1 += bias[col+1]; }
                    if (EPI == 2) { v0 = gelu_exact(v0); v1 = gelu_exact(v1); }
                    if (EPI == 1) { v0 += resid[rres+col]; v1 += resid[rres+col+1]; }
                    *(float2*)&Cm[(size_t)row * ldc + col] = make_float2(v0, v1);
                }
            }
        }
    }
}

// ------------- cls attention row (q0 = xn0 @ Wq, softmax, -> CLSH) ----------
__global__ __launch_bounds__(256) void cls_kernel(
    const float* __restrict__ XN, const float* __restrict__ wqkv,
    const float* __restrict__ QKV, const float* __restrict__ amask,
    float* __restrict__ CLSH)
{
    __shared__ float q0[64];
    __shared__ float sS[1024];
    __shared__ float red[8];
    int h = blockIdx.x, b = blockIdx.y, t = threadIdx.x;

    {
        int d = t >> 2, part = t & 3;
        const float* xr = XN + (size_t)b * N_ * C_;
        const float* wc = wqkv + h*64 + d;
        float s = 0.f;
        int k0 = part * 192;
        for (int k = k0; k < k0 + 192; k++)
            s = fmaf(xr[k], wc[(size_t)k * 2304], s);
        s += __shfl_xor_sync(~0u, s, 1);
        s += __shfl_xor_sync(~0u, s, 2);
        if (part == 0) q0[d] = s;
    }
    __syncthreads();

    float sv[4];
    #pragma unroll
    for (int j = 0; j < 4; j++) {
        int m = t + 256*j;
        const float* kr = QKV + (size_t)(b*N_ + m)*2304 + 768 + h*64;
        float acc = 0.f;
        #pragma unroll
        for (int d = 0; d < 64; d++) acc = fmaf(q0[d], kr[d], acc);
        sv[j] = acc * 0.125f;
    }
    float mx = fmaxf(fmaxf(sv[0], sv[1]), fmaxf(sv[2], sv[3]));
    #pragma unroll
    for (int o = 16; o; o >>= 1) mx = fmaxf(mx, __shfl_xor_sync(~0u, mx, o));
    if ((t & 31) == 0) red[t >> 5] = mx;
    __syncthreads();
    mx = red[0];
    #pragma unroll
    for (int i = 1; i < 8; i++) mx = fmaxf(mx, red[i]);

    const float* mrow = amask + (size_t)b * N_ * N_;
    float sum = 0.f;
    #pragma unroll
    for (int j = 0; j < 4; j++) {
        int m = t + 256*j;
        float e = expf(sv[j] - mx) * mrow[m];
        sS[m] = e;
        sum += e;
    }
    #pragma unroll
    for (int o = 16; o; o >>= 1) sum += __shfl_xor_sync(~0u, sum, o);
    __syncthreads();
    if ((t & 31) == 0) red[t >> 5] = sum;
    __syncthreads();
    sum = 0.f;
    #pragma unroll
    for (int i = 0; i < 8; i++) sum += red[i];
    float rinv = 1.0f / (sum + 1e-6f);
    const float epsn = 1e-6f / 1024.0f;
    float* cl = CLSH + (size_t)(b*H_ + h) * (N_ - 1);
    #pragma unroll
    for (int j = 0; j < 4; j++) {
        int m = t + 256*j;
        if (m >= 1) cl[m-1] = (sS[m] + epsn) * rinv;
    }
}

// ----------- K transpose: KT[b,h,d,m] <- QKV K region (tile transpose) ------
__global__ __launch_bounds__(256) void kT_kernel(
    const float* __restrict__ QKV, float* __restrict__ KT)
{
    __shared__ float tile[128][65];
    int mt = blockIdx.x, h = blockIdx.y, b = blockIdx.z, t = threadIdx.x;
    int m0 = mt * 128;
    {
        int row = t >> 1, d0 = (t & 1) * 32;
        const float* src = QKV + (size_t)(b*N_ + m0 + row)*2304 + 768 + h*64 + d0;
        #pragma unroll
        for (int j = 0; j < 8; j++) {
            float4 v = *(const float4*)(src + j*4);
            tile[row][d0 + j*4 + 0] = v.x;
            tile[row][d0 + j*4 + 1] = v.y;
            tile[row][d0 + j*4 + 2] = v.z;
            tile[row][d0 + j*4 + 3] = v.w;
        }
    }
    __syncthreads();
    {
        int lane = t & 31, w = t >> 5;
        for (int dr = w; dr < 64; dr += 8) {
            float4 v = make_float4(tile[lane*4+0][dr], tile[lane*4+1][dr],
                                   tile[lane*4+2][dr], tile[lane*4+3][dr]);
            *(float4*)(KT + ((size_t)(b*H_ + h)*64 + dr)*N_ + m0 + lane*4) = v;
        }
    }
}

// ===== Tensor-core attention for SELECTED rows: (32 rows, head, batch) ======
// scores in smem (no DRAM); QK and AV via bf16x3 m16n8k16; __expf softmax.
#define QA_STR 144   // 64 bf16 cols (128B) + 16 pad
#define PB_STR 272   // 128 bf16 cols (256B) + 16 pad
#define O_SS   0
#define O_QH   131072
#define O_QL   (131072 + 4608)
#define O_KH   (131072 + 9216)
#define O_KL   (131072 + 9216 + 17408)
#define O_PH   131072
#define O_PL   (131072 + 8704)
#define O_VH   (131072 + 17408)
#define O_VL   (131072 + 17408 + 18432)
#define ATTN2_SMEM (131072 + 17408 + 36864)   // 185344 B

__global__ __launch_bounds__(256) void attn_mma_kernel(
    const float* __restrict__ QG, const float* __restrict__ QKV,
    const float* __restrict__ KT, const float* __restrict__ amask,
    const int* __restrict__ ROWSEL, float* __restrict__ XATT)
{
    extern __shared__ char sm[];
    float* sS = (float*)(sm + O_SS);
    const uint32_t sb = smem_u32p(sm);
    const int t = threadIdx.x, lane = t & 31, wid = t >> 5;
    const int lq = lane >> 2, lr = lane & 3;
    const int n0 = blockIdx.x * 32, h = blockIdx.y, b = blockIdx.z;

    // ---- stage Q tile once: 32 rows x 64 d (bf16 hi/lo, row-major)
    {
        int row = t >> 3, d0 = (t & 7) * 8;
        float v[8];
        int r = n0 + row;
        if (r < RN_) {
            const float* src = QG + (size_t)(b*RN_ + r)*C_ + h*64 + d0;
            *(float4*)&v[0] = *(const float4*)src;
            *(float4*)&v[4] = *(const float4*)(src + 4);
        } else {
            #pragma unroll
            for (int j = 0; j < 8; j++) v[j] = 0.f;
        }
        uint32_t uh[4], ul[4];
        cvt8(v, uh, ul);
        *(uint4*)(sm + O_QH + row*QA_STR + d0*2) = make_uint4(uh[0],uh[1],uh[2],uh[3]);
        *(uint4*)(sm + O_QL + row*QA_STR + d0*2) = make_uint4(ul[0],ul[1],ul[2],ul[3]);
    }

    // ldmatrix base addresses
    const uint32_t arow = ((lane>>3)&1)*8 + (lane&7);
    const uint32_t ainc = (lane>>4)*16;
    const uint32_t aq_h = sb + O_QH + arow*QA_STR + ainc;
    const uint32_t aq_l = sb + O_QL + arow*QA_STR + ainc;
    const uint32_t bk_h = sb + O_KH + arow*PB_STR + wid*32 + ainc;
    const uint32_t bk_l = sb + O_KL + arow*PB_STR + wid*32 + ainc;

    // ============ phase 1: scores S = (Q K^T) * 0.125 ============
    for (int kt = 0; kt < 8; kt++) {
        __syncthreads();   // Q-stage (first iter) / prev-iter mma reads done
        {   // stage K tile: 64 d-rows x 128 m from KT (coalesced)
            int drow = t >> 2, m0 = (t & 3) * 32;
            const float* src = KT + ((size_t)(b*H_ + h)*64 + drow)*N_ + kt*128 + m0;
            #pragma unroll
            for (int j = 0; j < 4; j++) {
                float v[8];
                *(float4*)&v[0] = *(const float4*)(src + j*8);
                *(float4*)&v[4] = *(const float4*)(src + j*8 + 4);
                uint32_t uh[4], ul[4];
                cvt8(v, uh, ul);
                *(uint4*)(sm + O_KH + drow*PB_STR + (m0 + j*8)*2) = make_uint4(uh[0],uh[1],uh[2],uh[3]);
                *(uint4*)(sm + O_KL + drow*PB_STR + (m0 + j*8)*2) = make_uint4(ul[0],ul[1],ul[2],ul[3]);
            }
        }
        __syncthreads();

        float acc[2][2][4];
        #pragma unroll
        for (int i = 0; i < 2; i++)
            #pragma unroll
            for (int j = 0; j < 2; j++)
                #pragma unroll
                for (int q = 0; q < 4; q++) acc[i][j][q] = 0.f;

        #pragma unroll
        for (int ks = 0; ks < 4; ks++) {
            uint32_t ah[2][4], al_[2][4], bh[2][2], bl_[2][2];
            #pragma unroll
            for (int mf = 0; mf < 2; mf++) {
                LDSM_X4(ah[mf][0],ah[mf][1],ah[mf][2],ah[mf][3],
                        aq_h + mf*(16*QA_STR) + ks*32);
                LDSM_X4(al_[mf][0],al_[mf][1],al_[mf][2],al_[mf][3],
                        aq_l + mf*(16*QA_STR) + ks*32);
            }
            LDSM_X4T(bh[0][0],bh[0][1],bh[1][0],bh[1][1], bk_h + ks*(16*PB_STR));
            LDSM_X4T(bl_[0][0],bl_[0][1],bl_[1][0],bl_[1][1], bk_l + ks*(16*PB_STR));
            #pragma unroll
            for (int mf = 0; mf < 2; mf++)
                #pragma unroll
                for (int nf = 0; nf < 2; nf++) {
                    float* c = acc[mf][nf];
                    mma_bf16(c, ah[mf],  bh[nf][0],  bh[nf][1]);
                    mma_bf16(c, ah[mf],  bl_[nf][0], bl_[nf][1]);
                    mma_bf16(c, al_[mf], bh[nf][0],  bh[nf][1]);
                }
        }
        #pragma unroll
        for (int mf = 0; mf < 2; mf++)
            #pragma unroll
            for (int nf = 0; nf < 2; nf++) {
                int col = kt*128 + wid*16 + nf*8 + lr*2;
                sS[(mf*16 + lq)*1024 + col]     = acc[mf][nf][0]*0.125f;
                sS[(mf*16 + lq)*1024 + col + 1] = acc[mf][nf][1]*0.125f;
                sS[(mf*16 + lq + 8)*1024 + col]     = acc[mf][nf][2]*0.125f;
                sS[(mf*16 + lq + 8)*1024 + col + 1] = acc[mf][nf][3]*0.125f;
            }
    }
    __syncthreads();

    // ============ phase 2: softmax (jax variant, __expf — tolerant path) ====
    for (int rr = 0; rr < 4; rr++) {
        int i = wid + rr*8;
        int r = n0 + i;
        if (r >= RN_) continue;
        int norig = ROWSEL[b*RN_ + r] - b*1024;
        float* row = sS + i*1024;
        float mx = -3.4e38f;
        for (int m = lane; m < 1024; m += 32) mx = fmaxf(mx, row[m]);
        #pragma unroll
        for (int o = 16; o; o >>= 1) mx = fmaxf(mx, __shfl_xor_sync(~0u, mx, o));
        const float* mrow = amask + (size_t)(b * N_ + norig) * N_;
        float sum = 0.f;
        for (int m = lane; m < 1024; m += 32) {
            float e = __expf(row[m] - mx) * mrow[m];
            row[m] = e;
            sum += e;
        }
        #pragma unroll
        for (int o = 16; o; o >>= 1) sum += __shfl_xor_sync(~0u, sum, o);
        float rinv = 1.0f / (sum + 1e-6f);
        const float epsn = 1e-6f / 1024.0f;
        for (int m = lane; m < 1024; m += 32) row[m] = (row[m] + epsn) * rinv;
    }

    // ============ phase 3: AV ============
    const uint32_t ap_h = sb + O_PH + arow*PB_STR + ainc;
    const uint32_t ap_l = sb + O_PL + arow*PB_STR + ainc;
    const uint32_t bv_h = sb + O_VH + arow*QA_STR + wid*16;  // lanes 0-15 used by x2
    const uint32_t bv_l = sb + O_VL + arow*QA_STR + wid*16;

    float oacc[2][4] = {{0.f,0.f,0.f,0.f},{0.f,0.f,0.f,0.f}};

    for (int kt = 0; kt < 8; kt++) {
        __syncthreads();   // softmax (first iter) / prev mma reads done
        {   // convert P slice: 32 rows x 128 cols -> bf16 hi/lo
            int row = t >> 3, c0 = (t & 7) * 16;
            float v[16];
            const float* src = sS + row*1024 + kt*128 + c0;
            #pragma unroll
            for (int j = 0; j < 4; j++) *(float4*)&v[j*4] = *(const float4*)(src + j*4);
            uint32_t uh[8], ul[8];
            cvt16(v, uh, ul);
            char* p = sm + O_PH + row*PB_STR + c0*2;
            *(uint4*)p        = make_uint4(uh[0],uh[1],uh[2],uh[3]);
            *(uint4*)(p + 16) = make_uint4(uh[4],uh[5],uh[6],uh[7]);
            p = sm + O_PL + row*PB_STR + c0*2;
            *(uint4*)p        = make_uint4(ul[0],ul[1],ul[2],ul[3]);
            *(uint4*)(p + 16) = make_uint4(ul[4],ul[5],ul[6],ul[7]);
        }
        {   // stage V tile: 128 rows x 64 d (natural layout, coalesced)
            int vrow = t >> 1, d0 = (t & 1) * 32;
            const float* src = QKV + (size_t)(b*N_ + kt*128 + vrow)*2304 + 1536 + h*64 + d0;
            #pragma unroll
            for (int j = 0; j < 4; j++) {
                float v[8];
                *(float4*)&v[0] = *(const float4*)(src + j*8);
                *(float4*)&v[4] = *(const float4*)(src + j*8 + 4);
                uint32_t uh[4], ul[4];
                cvt8(v, uh, ul);
                *(uint4*)(sm + O_VH + vrow*QA_STR + (d0 + j*8)*2) = make_uint4(uh[0],uh[1],uh[2],uh[3]);
                *(uint4*)(sm + O_VL + vrow*QA_STR + (d0 + j*8)*2) = make_uint4(ul[0],ul[1],ul[2],ul[3]);
            }
        }
        __syncthreads();

        #pragma unroll
        for (int ks = 0; ks < 8; ks++) {
            uint32_t ah[2][4], al_[2][4], bh[2], bl_[2];
            #pragma unroll
            for (int mf = 0; mf < 2; mf++) {
                LDSM_X4(ah[mf][0],ah[mf][1],ah[mf][2],ah[mf][3],
                        ap_h + mf*(16*PB_STR) + ks*32);
                LDSM_X4(al_[mf][0],al_[mf][1],al_[mf][2],al_[mf][3],
                        ap_l + mf*(16*PB_STR) + ks*32);
            }
            LDSM_X2T(bh[0], bh[1], bv_h + ks*(16*QA_STR));
            LDSM_X2T(bl_[0], bl_[1], bv_l + ks*(16*QA_STR));
            #pragma unroll
            for (int mf = 0; mf < 2; mf++) {
                mma_bf16(oacc[mf], ah[mf],  bh[0],  bh[1]);
                mma_bf16(oacc[mf], ah[mf],  bl_[0], bl_[1]);
                mma_bf16(oacc[mf], al_[mf], bh[0],  bh[1]);
            }
        }
    }

    // write out: rows mf*16 + lq (+8), cols wid*8 + lr*2
    #pragma unroll
    for (int mf = 0; mf < 2; mf++)
        #pragma unroll
        for (int half = 0; half < 2; half++) {
            int r = n0 + mf*16 + lq + half*8;
            if (r < RN_) {
                int col = wid*8 + lr*2;
                *(float2*)&XATT[(size_t)(b*RN_ + r)*C_ + h*64 + col] =
                    make_float2(oacc[mf][half*2], oacc[mf][half*2+1]);
            }
        }
}

// ---------------- top-k via bitonic sort (jax.lax.top_k semantics) ----------
__global__ __launch_bounds__(256) void topk_kernel(
    const float* __restrict__ CLSH, int* __restrict__ ROWSEL,
    float* __restrict__ outIA, float* __restrict__ outIM)
{
    __shared__ float sv[1024];
    __shared__ int   si[1024];
    int seg = blockIdx.x, b = blockIdx.y, t = threadIdx.x;
    int P     = seg ? 1024 : 256;
    int count = seg ? 768  : 255;
    int base  = seg ? 255  : 0;

    for (int e = t; e < P; e += 256) {
        if (e < count) {
            float s = 0.f;
            #pragma unroll
            for (int hh = 0; hh < 12; hh++)
                s += CLSH[(size_t)(b*12 + hh) * 1023 + base + e];
            sv[e] = s;
            si[e] = e;
        } else { sv[e] = -3.4e38f; si[e] = 0x7FFFFFFF; }
    }

    for (int k = 2; k <= P; k <<= 1)
        for (int j = k >> 1; j > 0; j >>= 1) {
            __syncthreads();
            for (int i = t; i < P; i += 256) {
                int ixj = i ^ j;
                if (ixj > i) {
                    float v1 = sv[i], v2 = sv[ixj];
                    int a1 = si[i], a2 = si[ixj];
                    bool before12 = (v1 > v2) || (v1 == v2 && a1 < a2);
                    bool up = ((i & k) == 0);
                    if (up != before12) {
                        sv[i] = v2; sv[ixj] = v1; si[i] = a2; si[ixj] = a1;
                    }
                }
            }
        }
    __syncthreads();

    if (seg == 0) {
        if (t < 128) {
            int idx = si[t];
            if (outIA) outIA[b*128 + t] = (float)idx;
            ROWSEL[b*513 + 1 + t] = b*1024 + 1 + idx;
        }
        if (t == 0) ROWSEL[b*513] = b*1024;
    } else {
        for (int e = t; e < 384; e += 256) {
            int idx = si[e];
            if (outIM) outIM[b*384 + e] = (float)idx;
            ROWSEL[b*513 + 129 + e] = b*1024 + 256 + idx;
        }
    }
}

__global__ void fill_ones(float* __restrict__ p, int n) {
    int i = blockIdx.x * 256 + threadIdx.x;
    if (i < n) p[i] = 1.0f;
}

// ---------------- launcher ----------------
extern "C" void kernel_launch(void* const* d_in, const int* in_sizes, int n_in,
                              void* d_out, int out_size)
{
    const float* x      = (const float*)d_in[0];
    const float* amask  = (const float*)d_in[1];
    const float* w_qkv  = (const float*)d_in[4];
    const float* w_proj = (const float*)d_in[5];
    const float* b_proj = (const float*)d_in[6];
    const float* g1     = (const float*)d_in[7];
    const float* b1     = (const float*)d_in[8];
    const float* g2     = (const float*)d_in[9];
    const float* b2     = (const float*)d_in[10];
    const float* w_fc1  = (const float*)d_in[11];
    const float* b_fc1  = (const float*)d_in[12];
    const float* w_fc2  = (const float*)d_in[13];
    const float* b_fc2  = (const float*)d_in[14];
    float* out = (float*)d_out;

    float *XN, *QKV, *KT, *QG, *XATT, *CLSH, *XP, *XN2, *HB; int* ROWSEL;
    cudaGetSymbolAddress((void**)&XN,   g_XN);
    cudaGetSymbolAddress((void**)&QKV,  g_QKV);
    cudaGetSymbolAddress((void**)&KT,   g_KT);
    cudaGetSymbolAddress((void**)&QG,   g_QG);
    cudaGetSymbolAddress((void**)&XATT, g_XATT);
    cudaGetSymbolAddress((void**)&CLSH, g_CLSH);
    cudaGetSymbolAddress((void**)&XP,   g_XP);
    cudaGetSymbolAddress((void**)&XN2,  g_XN2);
    cudaGetSymbolAddress((void**)&HB,   g_HB);
    cudaGetSymbolAddress((void**)&ROWSEL, g_ROWSEL);

    cudaFuncSetAttribute(attn_mma_kernel,
        cudaFuncAttributeMaxDynamicSharedMemorySize, ATTN2_SMEM);

    const int OFF_IA = 8*513*768;
    const int OFF_IM = OFF_IA + 8*128;
    const int OFF_MK = OFF_IM + 8*384;
    const int MK_SZ  = 8*513*513;
    const int TOTAL  = OFF_MK + MK_SZ;
    float* outIA = (out_size >= TOTAL) ? out + OFF_IA : nullptr;
    float* outIM = (out_size >= TOTAL) ? out + OFF_IM : nullptr;

    // 1. LN1 (all rows)
    ln_kernel<<<B_*N_, 256>>>(x, g1, b1, XN);
    // 2a. K GEMM (fp32 EXACT — feeds cls scores -> top-k)
    sgemm2<false><<<dim3(6, 64), 256>>>(
        XN, C_, w_qkv + 768, 3*C_, QKV + 768, 3*C_, B_*N_, C_, C_, nullptr);
    // 2b. V GEMM (bf16x3 mma — tolerant)
    bf_gemm<false,false,0><<<dim3(6, 64), 256>>>(
        XN, C_, w_qkv + 1536, 3*C_, QKV + 1536, 3*C_, B_*N_, C_, C_,
        nullptr, nullptr, nullptr);
    // 2c. K transpose -> KT[b,h,d,m] (for tensor-core attention B operand)
    kT_kernel<<<dim3(8, H_, B_), 256>>>(QKV, KT);
    // 3. cls attention row (fp32 exact) -> CLSH
    cls_kernel<<<dim3(H_, B_), 256>>>(XN, w_qkv, QKV, amask, CLSH);
    // 4. top-k -> ROWSEL + idx outputs
    topk_kernel<<<dim3(2, B_), 256>>>(CLSH, ROWSEL, outIA, outIM);
    // 5. gathered Q GEMM (bf16x3)
    bf_gemm<true,false,0><<<dim3(6, 33), 256>>>(
        XN, C_, w_qkv, 3*C_, QG, C_, MROWS, C_, C_, nullptr, nullptr, ROWSEL);
    // 6. attention for selected rows (bf16x3 mma + __expf — tolerant)
    attn_mma_kernel<<<dim3((RN_+31)/32, H_, B_), 256, ATTN2_SMEM>>>(
        QG, QKV, KT, amask, ROWSEL, XATT);
    // 7. proj (bf16x3): XP = x[sel] + (XATT @ w_proj + b_proj)
    bf_gemm<false,true,1><<<dim3(6, 33), 256>>>(
        XATT, C_, w_proj, C_, XP, C_, MROWS, C_, C_, b_proj, x, ROWSEL);
    // 8. LN2
    ln_kernel<<<MROWS, 256>>>(XP, g2, b2, XN2);
    // 9. fc1 + GELU (bf16x3)
    bf_gemm<false,false,2><<<dim3(24, 33), 256>>>(
        XN2, C_, w_fc1, HID_, HB, HID_, MROWS, HID_, C_, b_fc1, nullptr, nullptr);
    // 10. fc2 + bias + residual -> d_out (bf16x3)
    bf_gemm<false,false,1><<<dim3(6, 33), 256>>>(
        HB, HID_, w_fc2, C_, out, C_, MROWS, C_, HID_, b_fc2, XP, nullptr);
    // 11. new_mask == all ones (proved in R4)
    if (out_size >= TOTAL)
        fill_ones<<<(MK_SZ + 255)/256, 256>>>(out + OFF_MK, MK_SZ);
}